// round 7
// baseline (speedup 1.0000x reference)
#include <cuda_runtime.h>
#include <cuda_bf16.h>
#include <math.h>

#define NMAX   50000
#define EMAX   800000
#define ETMAX  (EMAX + NMAX)
#define GMAX   1024

typedef unsigned long long ull;

// ---------------- scratch ----------------
__device__ __align__(16) float         g_h0 [NMAX * 64];   // relu(x@Wp+bp), fp32
__device__ __align__(16) __nv_bfloat16 g_xh1[NMAX * 128];  // h0@W1 (bf16 payload)
__device__ __align__(16) float         g_out1[NMAX * 128]; // h1 = elu(gat1), fp32
__device__ __align__(16) __nv_bfloat16 g_xh2[NMAX * 64];   // h1@W2 (bf16 payload)
__device__ float g_as1[NMAX * 4];
__device__ float g_ad1[NMAX * 4];
__device__ float g_as2[NMAX];
__device__ float g_ad2[NMAX];
__device__ int   g_offs[NMAX + 1];
__device__ int   g_cursor[NMAX + 1];
__device__ int   g_csrc[ETMAX];
__device__ float g_pool[GMAX * 64];
__device__ float g_cnt [GMAX];
__device__ int   g_is64;

// ---------------- helpers ----------------
__device__ __forceinline__ int ld_idx(const void* p, long long i, int is64) {
    if (is64) return (int)((const long long*)p)[i];
    return ((const int*)p)[i];
}
__device__ __forceinline__ float eluf(float v) { return v > 0.f ? v : expm1f(v); }
__device__ __forceinline__ float warp_sum(float v) {
    #pragma unroll
    for (int o = 16; o > 0; o >>= 1) v += __shfl_down_sync(0xffffffffu, v, o);
    return v;
}
__device__ __forceinline__ unsigned pack_bf16x2(float a, float b) {
    __nv_bfloat162 p = __float22bfloat162_rn(make_float2(a, b));
    return *reinterpret_cast<unsigned*>(&p);
}
__device__ __forceinline__ float2 unpack_bf16x2(unsigned u) {
    __nv_bfloat162 p = *reinterpret_cast<__nv_bfloat162*>(&u);
    return __bfloat1622float2(p);
}
// packed fp32x2 FMA (FFMA2) — only reachable via PTX
__device__ __forceinline__ void fma2(ull& d, ull a, ull b) {
    asm("fma.rn.f32x2 %0, %1, %2, %3;" : "=l"(d) : "l"(a), "l"(b), "l"(d));
}
__device__ __forceinline__ float2 u2f(ull v) {
    float2 r;
    asm("mov.b64 {%0, %1}, %2;" : "=f"(r.x), "=f"(r.y) : "l"(v));
    return r;
}

// ---------------- init: zero scratch + dtype detect ----------------
__global__ void k_init(const void* ei, int n, int G) {
    if (blockIdx.x == 0 && threadIdx.x < 32) {
        const int* p = (const int*)ei;
        bool all0 = true;
        for (int i = threadIdx.x; i < 128; i += 32)
            if (p[2 * i + 1] != 0) all0 = false;
        all0 = __all_sync(0xffffffffu, all0);
        if (threadIdx.x == 0) g_is64 = all0 ? 1 : 0;
    }
    int total = (n + 1) + G * 64 + G;
    for (int i = blockIdx.x * blockDim.x + threadIdx.x; i < total; i += gridDim.x * blockDim.x) {
        if (i <= n)                 g_offs[i] = 0;
        else if (i <= n + G * 64)   g_pool[i - n - 1] = 0.f;
        else                        g_cnt [i - n - 1 - G * 64] = 0.f;
    }
}

// ---------------- CSR build ----------------
__global__ void k_hist(const void* __restrict__ ei, int e, int et) {
    int base = (blockIdx.x * blockDim.x + threadIdx.x) * 4;
    if (base >= et) return;
    int is64 = g_is64;
    #pragma unroll
    for (int u = 0; u < 4; u++) {
        int idx = base + u;
        if (idx >= et) break;
        int d = (idx < e) ? ld_idx(ei, (long long)e + idx, is64) : (idx - e);
        atomicAdd(&g_offs[d + 1], 1);
    }
}

__global__ void k_scan(int n1) {
    __shared__ int part[1024];
    int t = threadIdx.x;
    int chunk = (n1 + 1023) >> 10;
    int beg = t * chunk;
    int end = beg + chunk; if (end > n1) end = n1;
    int s = 0;
    for (int i = beg; i < end; i++) s += g_offs[i];
    part[t] = s;
    __syncthreads();
    for (int off = 1; off < 1024; off <<= 1) {
        int v = (t >= off) ? part[t - off] : 0;
        __syncthreads();
        part[t] += v;
        __syncthreads();
    }
    int run = (t == 0) ? 0 : part[t - 1];
    for (int i = beg; i < end; i++) {
        run += g_offs[i];
        g_offs[i] = run;
        g_cursor[i] = run;
    }
}

__global__ void k_place(const void* __restrict__ ei, int e, int et) {
    int base = (blockIdx.x * blockDim.x + threadIdx.x) * 8;
    if (base >= et) return;
    int is64 = g_is64;
    int sv[8], dv[8];
    int m = et - base; if (m > 8) m = 8;
    #pragma unroll
    for (int u = 0; u < 8; u++) {
        if (u >= m) break;
        int idx = base + u;
        if (idx < e) { sv[u] = ld_idx(ei, idx, is64); dv[u] = ld_idx(ei, (long long)e + idx, is64); }
        else         { sv[u] = dv[u] = idx - e; }
    }
    int pos[8];
    #pragma unroll
    for (int u = 0; u < 8; u++) {
        if (u >= m) break;
        pos[u] = atomicAdd(&g_cursor[dv[u]], 1);
    }
    #pragma unroll
    for (int u = 0; u < 8; u++) {
        if (u >= m) break;
        g_csrc[pos[u]] = sv[u];
    }
}

// ============ GEMM A[n,128] @ W[128,64], 64 rows/block, FFMA2 ============
// mode 0: out fp32 = relu(acc + bias)  (node projection)
// mode 1: out bf16 = acc; g_as2/g_ad2 = acc@av_s / acc@av_d
// dyn smem: sW2[128][128] (W splat-duplicated) + sAt[128][68]
__global__ void __launch_bounds__(256) k_gemm_k128_m64(
        const float* __restrict__ A, const float* __restrict__ W,
        const float* __restrict__ bias,
        const float* __restrict__ av_s, const float* __restrict__ av_d,
        void* __restrict__ outp, int n, int mode) {
    extern __shared__ float sm[];
    float* sW2 = sm;               // [128][128]: sW2[k][2c]=sW2[k][2c+1]=W[k][c]
    float* sAt = sm + 128 * 128;   // [k][r] stride 68
    int t = threadIdx.x;           // 256
    for (int i = t; i < 128 * 64; i += 256) {
        int k = i >> 6, c = i & 63;
        float v = W[i];
        *(float2*)&sW2[k * 128 + 2 * c] = make_float2(v, v);
    }
    int row0 = blockIdx.x * 64;
    for (int i = t; i < 64 * 128; i += 256) {
        int r = i >> 7, k = i & 127;
        float v = (row0 + r < n) ? A[(size_t)(row0 + r) * 128 + k] : 0.f;
        sAt[k * 68 + r] = v;
    }
    __syncthreads();
    int cg = t & 15, rg = t >> 4;
    int c0 = cg * 4, r0 = rg * 4;
    ull acc[2][4] = {{0ULL,0ULL,0ULL,0ULL},{0ULL,0ULL,0ULL,0ULL}};
    #pragma unroll 4
    for (int k = 0; k < 128; k++) {
        ulonglong2 ap = *(const ulonglong2*)&sAt[k * 68 + r0];       // rows (r0,r0+1),(r0+2,r0+3)
        const ull* wp = (const ull*)&sW2[k * 128 + 2 * c0];
        ulonglong2 wA = *(const ulonglong2*)wp;                       // splat(c0), splat(c0+1)
        ulonglong2 wB = *(const ulonglong2*)(wp + 2);                 // splat(c0+2), splat(c0+3)
        fma2(acc[0][0], ap.x, wA.x); fma2(acc[0][1], ap.x, wA.y);
        fma2(acc[0][2], ap.x, wB.x); fma2(acc[0][3], ap.x, wB.y);
        fma2(acc[1][0], ap.y, wA.x); fma2(acc[1][1], ap.y, wA.y);
        fma2(acc[1][2], ap.y, wB.x); fma2(acc[1][3], ap.y, wB.y);
    }
    // unpack to per-row float4
    float4 accs[4];
    {
        float2 p00 = u2f(acc[0][0]), p01 = u2f(acc[0][1]), p02 = u2f(acc[0][2]), p03 = u2f(acc[0][3]);
        float2 p10 = u2f(acc[1][0]), p11 = u2f(acc[1][1]), p12 = u2f(acc[1][2]), p13 = u2f(acc[1][3]);
        accs[0] = make_float4(p00.x, p01.x, p02.x, p03.x);
        accs[1] = make_float4(p00.y, p01.y, p02.y, p03.y);
        accs[2] = make_float4(p10.x, p11.x, p12.x, p13.x);
        accs[3] = make_float4(p10.y, p11.y, p12.y, p13.y);
    }
    if (mode == 0) {
        float* out = (float*)outp;
        float4 bb;
        bb.x = bias[c0]; bb.y = bias[c0+1]; bb.z = bias[c0+2]; bb.w = bias[c0+3];
        #pragma unroll
        for (int j = 0; j < 4; j++) {
            int row = row0 + r0 + j;
            if (row < n) {
                float4 o = accs[j];
                o.x = fmaxf(o.x + bb.x, 0.f); o.y = fmaxf(o.y + bb.y, 0.f);
                o.z = fmaxf(o.z + bb.z, 0.f); o.w = fmaxf(o.w + bb.w, 0.f);
                *(float4*)&out[(size_t)row * 64 + c0] = o;
            }
        }
    } else {
        __nv_bfloat16* out = (__nv_bfloat16*)outp;
        float4 sv, dv;
        sv.x = av_s[c0]; sv.y = av_s[c0+1]; sv.z = av_s[c0+2]; sv.w = av_s[c0+3];
        dv.x = av_d[c0]; dv.y = av_d[c0+1]; dv.z = av_d[c0+2]; dv.w = av_d[c0+3];
        #pragma unroll
        for (int j = 0; j < 4; j++) {
            int row = row0 + r0 + j;
            float4 o = accs[j];
            float ps = o.x*sv.x + o.y*sv.y + o.z*sv.z + o.w*sv.w;
            float pd = o.x*dv.x + o.y*dv.y + o.z*dv.z + o.w*dv.w;
            #pragma unroll
            for (int off = 1; off < 16; off <<= 1) {
                ps += __shfl_xor_sync(0xffffffffu, ps, off);
                pd += __shfl_xor_sync(0xffffffffu, pd, off);
            }
            if (row < n) {
                uint2 pk;
                pk.x = pack_bf16x2(o.x, o.y);
                pk.y = pack_bf16x2(o.z, o.w);
                *(uint2*)&out[(size_t)row * 64 + c0] = pk;
                if (cg == 0) { g_as2[row] = ps; g_ad2[row] = pd; }
            }
        }
    }
}

// ============ GEMM A[n,64] @ W1[64,128] -> bf16 xh1 + att1, FFMA2 ============
// dyn smem: sW2[64][256] (splat-dup) + sAt[64][68]
__global__ void __launch_bounds__(256) k_gemm_k64_m128(
        const float* __restrict__ A, const float* __restrict__ W,
        const float* __restrict__ av_s, const float* __restrict__ av_d,
        __nv_bfloat16* __restrict__ out, int n) {
    extern __shared__ float sm[];
    float* sW2 = sm;               // [64][256]
    float* sAt = sm + 64 * 256;    // [k][r] stride 68
    int t = threadIdx.x;           // 256
    for (int i = t; i < 64 * 128; i += 256) {
        int k = i >> 7, c = i & 127;
        float v = W[i];
        *(float2*)&sW2[k * 256 + 2 * c] = make_float2(v, v);
    }
    int row0 = blockIdx.x * 64;
    for (int i = t; i < 64 * 64; i += 256) {
        int r = i >> 6, k = i & 63;
        float v = (row0 + r < n) ? A[(size_t)(row0 + r) * 64 + k] : 0.f;
        sAt[k * 68 + r] = v;
    }
    __syncthreads();
    int cg = t & 15, rg = t >> 4;
    int c0 = cg * 8, r0 = rg * 4;
    ull acc[2][8];
    #pragma unroll
    for (int p = 0; p < 2; p++)
        #pragma unroll
        for (int c = 0; c < 8; c++) acc[p][c] = 0ULL;
    #pragma unroll 2
    for (int k = 0; k < 64; k++) {
        ulonglong2 ap = *(const ulonglong2*)&sAt[k * 68 + r0];
        const ull* wp = (const ull*)&sW2[k * 256 + 2 * c0];
        ulonglong2 w0 = *(const ulonglong2*)wp;
        ulonglong2 w1 = *(const ulonglong2*)(wp + 2);
        ulonglong2 w2 = *(const ulonglong2*)(wp + 4);
        ulonglong2 w3 = *(const ulonglong2*)(wp + 6);
        fma2(acc[0][0], ap.x, w0.x); fma2(acc[0][1], ap.x, w0.y);
        fma2(acc[0][2], ap.x, w1.x); fma2(acc[0][3], ap.x, w1.y);
        fma2(acc[0][4], ap.x, w2.x); fma2(acc[0][5], ap.x, w2.y);
        fma2(acc[0][6], ap.x, w3.x); fma2(acc[0][7], ap.x, w3.y);
        fma2(acc[1][0], ap.y, w0.x); fma2(acc[1][1], ap.y, w0.y);
        fma2(acc[1][2], ap.y, w1.x); fma2(acc[1][3], ap.y, w1.y);
        fma2(acc[1][4], ap.y, w2.x); fma2(acc[1][5], ap.y, w2.y);
        fma2(acc[1][6], ap.y, w3.x); fma2(acc[1][7], ap.y, w3.y);
    }
    int head = cg >> 2;
    float4 s0, s1, d0, d1;
    s0.x=av_s[c0];   s0.y=av_s[c0+1]; s0.z=av_s[c0+2]; s0.w=av_s[c0+3];
    s1.x=av_s[c0+4]; s1.y=av_s[c0+5]; s1.z=av_s[c0+6]; s1.w=av_s[c0+7];
    d0.x=av_d[c0];   d0.y=av_d[c0+1]; d0.z=av_d[c0+2]; d0.w=av_d[c0+3];
    d1.x=av_d[c0+4]; d1.y=av_d[c0+5]; d1.z=av_d[c0+6]; d1.w=av_d[c0+7];
    #pragma unroll
    for (int p = 0; p < 2; p++) {
        float2 q[8];
        #pragma unroll
        for (int c = 0; c < 8; c++) q[c] = u2f(acc[p][c]);
        #pragma unroll
        for (int half = 0; half < 2; half++) {
            int row = row0 + r0 + p * 2 + half;
            float4 oa, ob;
            if (half == 0) {
                oa = make_float4(q[0].x, q[1].x, q[2].x, q[3].x);
                ob = make_float4(q[4].x, q[5].x, q[6].x, q[7].x);
            } else {
                oa = make_float4(q[0].y, q[1].y, q[2].y, q[3].y);
                ob = make_float4(q[4].y, q[5].y, q[6].y, q[7].y);
            }
            float ps = oa.x*s0.x + oa.y*s0.y + oa.z*s0.z + oa.w*s0.w
                     + ob.x*s1.x + ob.y*s1.y + ob.z*s1.z + ob.w*s1.w;
            float pd = oa.x*d0.x + oa.y*d0.y + oa.z*d0.z + oa.w*d0.w
                     + ob.x*d1.x + ob.y*d1.y + ob.z*d1.z + ob.w*d1.w;
            ps += __shfl_xor_sync(0xffffffffu, ps, 1);
            ps += __shfl_xor_sync(0xffffffffu, ps, 2);
            pd += __shfl_xor_sync(0xffffffffu, pd, 1);
            pd += __shfl_xor_sync(0xffffffffu, pd, 2);
            if (row < n) {
                uint4 pk;
                pk.x = pack_bf16x2(oa.x, oa.y);
                pk.y = pack_bf16x2(oa.z, oa.w);
                pk.z = pack_bf16x2(ob.x, ob.y);
                pk.w = pack_bf16x2(ob.z, ob.w);
                *(uint4*)&out[(size_t)row * 128 + c0] = pk;
                if ((cg & 3) == 0) {
                    g_as1[row * 4 + head] = ps;
                    g_ad1[row * 4 + head] = pd;
                }
            }
        }
    }
}

// ---------------- GAT1 aggregation: warp per dst node (bf16 payload) ----------------
__global__ void k_agg1(const float* __restrict__ b1, int n) {
    int node = blockIdx.x * 8 + (threadIdx.x >> 5);
    if (node >= n) return;
    int lane = threadIdx.x & 31;
    int h = lane >> 3;
    float ad = g_ad1[node * 4 + h];
    int beg = g_offs[node], end = g_offs[node + 1];
    const uint2* xh = (const uint2*)g_xh1;
    float4 acc[4];
    acc[0] = make_float4(0.f,0.f,0.f,0.f); acc[1] = acc[0]; acc[2] = acc[0]; acc[3] = acc[0];
    float ws[4] = {0.f, 0.f, 0.f, 0.f};
    int j = beg;
    for (; j + 3 < end; j += 4) {
        int s[4];
        s[0] = g_csrc[j]; s[1] = g_csrc[j+1]; s[2] = g_csrc[j+2]; s[3] = g_csrc[j+3];
        #pragma unroll
        for (int u = 0; u < 4; u++) {
            float e = g_as1[s[u] * 4 + h] + ad;
            e = e > 0.f ? e : 0.2f * e;
            float w = __expf(e);
            uint2 pv = xh[(size_t)s[u] * 32 + lane];
            float2 v0 = unpack_bf16x2(pv.x);
            float2 v1 = unpack_bf16x2(pv.y);
            acc[u].x += w*v0.x; acc[u].y += w*v0.y; acc[u].z += w*v1.x; acc[u].w += w*v1.y;
            ws[u] += w;
        }
    }
    for (; j < end; j++) {
        int s0 = g_csrc[j];
        float e = g_as1[s0 * 4 + h] + ad;
        e = e > 0.f ? e : 0.2f * e;
        float w = __expf(e);
        uint2 pv = xh[(size_t)s0 * 32 + lane];
        float2 v0 = unpack_bf16x2(pv.x);
        float2 v1 = unpack_bf16x2(pv.y);
        acc[0].x += w*v0.x; acc[0].y += w*v0.y; acc[0].z += w*v1.x; acc[0].w += w*v1.y;
        ws[0] += w;
    }
    float inv = 1.f / (ws[0] + ws[1] + ws[2] + ws[3] + 1e-16f);
    float4 bb = ((const float4*)b1)[lane];
    float4 o;
    o.x = eluf((acc[0].x + acc[1].x + acc[2].x + acc[3].x) * inv + bb.x);
    o.y = eluf((acc[0].y + acc[1].y + acc[2].y + acc[3].y) * inv + bb.y);
    o.z = eluf((acc[0].z + acc[1].z + acc[2].z + acc[3].z) * inv + bb.z);
    o.w = eluf((acc[0].w + acc[1].w + acc[2].w + acc[3].w) * inv + bb.w);
    ((float4*)g_out1)[(size_t)node * 32 + lane] = o;
}

// ---------------- GAT2 aggregation + elu + mean-pool scatter ----------------
__global__ void k_agg2(const float* __restrict__ b2, const void* __restrict__ batch, int n) {
    int node = blockIdx.x * 8 + (threadIdx.x >> 5);
    if (node >= n) return;
    int lane = threadIdx.x & 31;
    float ad = g_ad2[node];
    int beg = g_offs[node], end = g_offs[node + 1];
    const unsigned* xh = (const unsigned*)g_xh2;
    float2 acc[4];
    acc[0] = make_float2(0.f,0.f); acc[1] = acc[0]; acc[2] = acc[0]; acc[3] = acc[0];
    float ws[4] = {0.f, 0.f, 0.f, 0.f};
    int j = beg;
    for (; j + 3 < end; j += 4) {
        int s[4];
        s[0] = g_csrc[j]; s[1] = g_csrc[j+1]; s[2] = g_csrc[j+2]; s[3] = g_csrc[j+3];
        #pragma unroll
        for (int u = 0; u < 4; u++) {
            float e = g_as2[s[u]] + ad;
            e = e > 0.f ? e : 0.2f * e;
            float w = __expf(e);
            float2 v = unpack_bf16x2(xh[(size_t)s[u] * 32 + lane]);
            acc[u].x += w*v.x; acc[u].y += w*v.y;
            ws[u] += w;
        }
    }
    for (; j < end; j++) {
        int s0 = g_csrc[j];
        float e = g_as2[s0] + ad;
        e = e > 0.f ? e : 0.2f * e;
        float w = __expf(e);
        float2 v = unpack_bf16x2(xh[(size_t)s0 * 32 + lane]);
        acc[0].x += w*v.x; acc[0].y += w*v.y;
        ws[0] += w;
    }
    float inv = 1.f / (ws[0] + ws[1] + ws[2] + ws[3] + 1e-16f);
    float2 bb = ((const float2*)b2)[lane];
    float ox = eluf((acc[0].x + acc[1].x + acc[2].x + acc[3].x) * inv + bb.x);
    float oy = eluf((acc[0].y + acc[1].y + acc[2].y + acc[3].y) * inv + bb.y);
    int b = ld_idx(batch, node, g_is64);
    atomicAdd(&g_pool[b * 64 + lane * 2], ox);
    atomicAdd(&g_pool[b * 64 + lane * 2 + 1], oy);
    if (lane == 0) atomicAdd(&g_cnt[b], 1.0f);
}

// ---------------- graph-level MLP + heads ----------------
__global__ void k_mlp(const float* __restrict__ Wm1, const float* __restrict__ bm1,
                      const float* __restrict__ Wm2, const float* __restrict__ bm2,
                      const float* __restrict__ Wc,  const float* __restrict__ bc,
                      const float* __restrict__ Wr,  const float* __restrict__ br,
                      const float* __restrict__ Wv,  const float* __restrict__ bv,
                      float* __restrict__ out, int G) {
    int g = blockIdx.x;
    int c = threadIdx.x;   // 64 threads
    __shared__ float hg[64], z1[64], z2[64];
    __shared__ float part[6];
    float cnt = fmaxf(g_cnt[g], 1.f);
    hg[c] = g_pool[g * 64 + c] / cnt;
    __syncthreads();
    float acc = bm1[c];
    #pragma unroll 8
    for (int k = 0; k < 64; k++) acc += hg[k] * Wm1[k * 64 + c];
    z1[c] = fmaxf(acc, 0.f);
    __syncthreads();
    acc = bm2[c];
    #pragma unroll 8
    for (int k = 0; k < 64; k++) acc += z1[k] * Wm2[k * 64 + c];
    z2[c] = fmaxf(acc, 0.f);
    __syncthreads();
    float vc = warp_sum(z2[c] * Wc[c]);
    float vr = warp_sum(z2[c] * Wr[c]);
    float vv = warp_sum(z2[c] * Wv[c]);
    if ((c & 31) == 0) {
        int w = c >> 5;
        part[w * 3 + 0] = vc; part[w * 3 + 1] = vr; part[w * 3 + 2] = vv;
    }
    __syncthreads();
    if (c == 0) {
        float cl = part[0] + part[3] + bc[0];
        float rt = part[1] + part[4] + br[0];
        float vo = part[2] + part[5] + bv[0];
        out[g]         = cl;
        out[G + g]     = rt;
        out[2 * G + g] = fmaxf(vo, 0.f) + log1pf(expf(-fabsf(vo)));  // softplus
    }
}

// ---------------- launch ----------------
extern "C" void kernel_launch(void* const* d_in, const int* in_sizes, int n_in,
                              void* d_out, int out_size) {
    const float* x    = (const float*)d_in[0];
    const void*  ei   = d_in[1];
    const void*  batch= d_in[2];
    const float* Wp   = (const float*)d_in[3];
    const float* bp   = (const float*)d_in[4];
    const float* W1   = (const float*)d_in[5];
    const float* as1  = (const float*)d_in[6];
    const float* ad1  = (const float*)d_in[7];
    const float* b1   = (const float*)d_in[8];
    const float* W2   = (const float*)d_in[9];
    const float* as2  = (const float*)d_in[10];
    const float* ad2  = (const float*)d_in[11];
    const float* b2   = (const float*)d_in[12];
    const float* Wm1  = (const float*)d_in[13];
    const float* bm1  = (const float*)d_in[14];
    const float* Wm2  = (const float*)d_in[15];
    const float* bm2  = (const float*)d_in[16];
    const float* Wc   = (const float*)d_in[17];
    const float* bc   = (const float*)d_in[18];
    const float* Wr   = (const float*)d_in[19];
    const float* br   = (const float*)d_in[20];
    const float* Wv   = (const float*)d_in[21];
    const float* bv   = (const float*)d_in[22];
    float* out = (float*)d_out;

    int n  = in_sizes[0] / 128;
    int e  = in_sizes[1] / 2;
    int G  = out_size / 3;
    int et = e + n;

    void *p_h0, *p_xh1, *p_out1, *p_xh2;
    cudaGetSymbolAddress(&p_h0,   g_h0);
    cudaGetSymbolAddress(&p_xh1,  g_xh1);
    cudaGetSymbolAddress(&p_out1, g_out1);
    cudaGetSymbolAddress(&p_xh2,  g_xh2);
    float*         d_h0   = (float*)p_h0;
    __nv_bfloat16* d_xh1  = (__nv_bfloat16*)p_xh1;
    float*         d_out1 = (float*)p_out1;
    __nv_bfloat16* d_xh2  = (__nv_bfloat16*)p_xh2;

    const int G128_SMEM = (128 * 128 + 128 * 68) * (int)sizeof(float);  // 100,352 B
    const int G64_SMEM  = (64 * 256 + 64 * 68)  * (int)sizeof(float);   //  82,944 B
    cudaFuncSetAttribute(k_gemm_k128_m64, cudaFuncAttributeMaxDynamicSharedMemorySize, G128_SMEM);
    cudaFuncSetAttribute(k_gemm_k64_m128, cudaFuncAttributeMaxDynamicSharedMemorySize, G64_SMEM);

    // fork: CSR chain (default) || GEMM chain (s2)
    cudaStream_t s2;
    cudaStreamCreateWithFlags(&s2, cudaStreamNonBlocking);
    cudaEvent_t evFork, evJoin;
    cudaEventCreateWithFlags(&evFork, cudaEventDisableTiming);
    cudaEventCreateWithFlags(&evJoin, cudaEventDisableTiming);

    cudaEventRecord(evFork, 0);
    cudaStreamWaitEvent(s2, evFork, 0);

    // chain B (s2): node projection + xh1 GEMM
    k_gemm_k128_m64<<<(n + 63) / 64, 256, G128_SMEM, s2>>>(x, Wp, bp, nullptr, nullptr, d_h0, n, 0);
    k_gemm_k64_m128<<<(n + 63) / 64, 256, G64_SMEM, s2>>>(d_h0, W1, as1, ad1, d_xh1, n);
    cudaEventRecord(evJoin, s2);

    // chain A (default): init + CSR build
    k_init <<<160, 256>>>(ei, n, G);
    k_hist <<<(et + 1023) / 1024, 256>>>(ei, e, et);
    k_scan <<<1, 1024>>>(n + 1);
    k_place<<<(et + 2047) / 2048, 256>>>(ei, e, et);

    // join
    cudaStreamWaitEvent(0, evJoin, 0);
    k_agg1<<<(n + 7) / 8, 256>>>(b1, n);
    k_gemm_k128_m64<<<(n + 63) / 64, 256, G128_SMEM>>>(d_out1, W2, nullptr, as2, ad2, d_xh2, n, 1);
    k_agg2<<<(n + 7) / 8, 256>>>(b2, batch, n);
    k_mlp<<<G, 64>>>(Wm1, bm1, Wm2, bm2, Wc, bc, Wr, br, Wv, bv, out, G);
}

// round 8
// speedup vs baseline: 1.3351x; 1.3351x over previous
#include <cuda_runtime.h>
#include <cuda_bf16.h>
#include <math.h>

#define NMAX   50000
#define EMAX   800000
#define ETMAX  (EMAX + NMAX)
#define GMAX   1024

typedef unsigned long long ull;

// ---------------- scratch ----------------
__device__ __align__(16) float         g_h0 [NMAX * 64];   // relu(x@Wp+bp), fp32
__device__ __align__(16) __nv_bfloat16 g_xh1[NMAX * 128];  // h0@W1 (bf16 payload)
__device__ __align__(16) float         g_out1[NMAX * 128]; // h1 = elu(gat1), fp32
__device__ __align__(16) __nv_bfloat16 g_xh2[NMAX * 64];   // h1@W2 (bf16 payload)
__device__ float g_as1[NMAX * 4];
__device__ float g_ad1[NMAX * 4];
__device__ float g_as2[NMAX];
__device__ float g_ad2[NMAX];
__device__ int   g_offs[NMAX + 1];
__device__ int   g_cursor[NMAX + 1];
__device__ int   g_csrc[ETMAX];
__device__ float g_pool[GMAX * 64];
__device__ float g_cnt [GMAX];
__device__ int   g_is64;

// ---------------- helpers ----------------
__device__ __forceinline__ int ld_idx(const void* p, long long i, int is64) {
    if (is64) return (int)((const long long*)p)[i];
    return ((const int*)p)[i];
}
__device__ __forceinline__ float eluf(float v) { return v > 0.f ? v : expm1f(v); }
__device__ __forceinline__ float warp_sum(float v) {
    #pragma unroll
    for (int o = 16; o > 0; o >>= 1) v += __shfl_down_sync(0xffffffffu, v, o);
    return v;
}
__device__ __forceinline__ unsigned pack_bf16x2(float a, float b) {
    __nv_bfloat162 p = __float22bfloat162_rn(make_float2(a, b));
    return *reinterpret_cast<unsigned*>(&p);
}
__device__ __forceinline__ float2 unpack_bf16x2(unsigned u) {
    __nv_bfloat162 p = *reinterpret_cast<__nv_bfloat162*>(&u);
    return __bfloat1622float2(p);
}
// packed fp32x2 FMA (FFMA2) — only reachable via PTX
__device__ __forceinline__ void fma2(ull& d, ull a, ull b) {
    asm("fma.rn.f32x2 %0, %1, %2, %3;" : "=l"(d) : "l"(a), "l"(b), "l"(d));
}
__device__ __forceinline__ ull splat2(float a) {
    ull r;
    asm("mov.b64 %0, {%1, %1};" : "=l"(r) : "f"(a));
    return r;
}
__device__ __forceinline__ float2 u2f(ull v) {
    float2 r;
    asm("mov.b64 {%0, %1}, %2;" : "=f"(r.x), "=f"(r.y) : "l"(v));
    return r;
}

// ---------------- init: zero scratch + dtype detect ----------------
__global__ void k_init(const void* ei, int n, int G) {
    if (blockIdx.x == 0 && threadIdx.x < 32) {
        const int* p = (const int*)ei;
        bool all0 = true;
        for (int i = threadIdx.x; i < 128; i += 32)
            if (p[2 * i + 1] != 0) all0 = false;
        all0 = __all_sync(0xffffffffu, all0);
        if (threadIdx.x == 0) g_is64 = all0 ? 1 : 0;
    }
    int total = (n + 1) + G * 64 + G;
    for (int i = blockIdx.x * blockDim.x + threadIdx.x; i < total; i += gridDim.x * blockDim.x) {
        if (i <= n)                 g_offs[i] = 0;
        else if (i <= n + G * 64)   g_pool[i - n - 1] = 0.f;
        else                        g_cnt [i - n - 1 - G * 64] = 0.f;
    }
}

// ---------------- CSR build ----------------
__global__ void k_hist(const void* __restrict__ ei, int e, int et) {
    int base = (blockIdx.x * blockDim.x + threadIdx.x) * 4;
    if (base >= et) return;
    int is64 = g_is64;
    #pragma unroll
    for (int u = 0; u < 4; u++) {
        int idx = base + u;
        if (idx >= et) break;
        int d = (idx < e) ? ld_idx(ei, (long long)e + idx, is64) : (idx - e);
        atomicAdd(&g_offs[d + 1], 1);
    }
}

__global__ void k_scan(int n1) {
    __shared__ int part[1024];
    int t = threadIdx.x;
    int chunk = (n1 + 1023) >> 10;
    int beg = t * chunk;
    int end = beg + chunk; if (end > n1) end = n1;
    int s = 0;
    for (int i = beg; i < end; i++) s += g_offs[i];
    part[t] = s;
    __syncthreads();
    for (int off = 1; off < 1024; off <<= 1) {
        int v = (t >= off) ? part[t - off] : 0;
        __syncthreads();
        part[t] += v;
        __syncthreads();
    }
    int run = (t == 0) ? 0 : part[t - 1];
    for (int i = beg; i < end; i++) {
        run += g_offs[i];
        g_offs[i] = run;
        g_cursor[i] = run;
    }
}

__global__ void k_place(const void* __restrict__ ei, int e, int et) {
    int base = (blockIdx.x * blockDim.x + threadIdx.x) * 8;
    if (base >= et) return;
    int is64 = g_is64;
    int sv[8], dv[8];
    int m = et - base; if (m > 8) m = 8;
    #pragma unroll
    for (int u = 0; u < 8; u++) {
        if (u >= m) break;
        int idx = base + u;
        if (idx < e) { sv[u] = ld_idx(ei, idx, is64); dv[u] = ld_idx(ei, (long long)e + idx, is64); }
        else         { sv[u] = dv[u] = idx - e; }
    }
    int pos[8];
    #pragma unroll
    for (int u = 0; u < 8; u++) {
        if (u >= m) break;
        pos[u] = atomicAdd(&g_cursor[dv[u]], 1);
    }
    #pragma unroll
    for (int u = 0; u < 8; u++) {
        if (u >= m) break;
        g_csrc[pos[u]] = sv[u];
    }
}

// ============ GEMM A[n,128] @ W[128,64], 64 rows/block, 128 thr ============
// column-pair FFMA2: acc[row][cp] = (col 2cp, col 2cp+1); W pairs natural, A splat.
// mode 0: out fp32 = relu(acc + bias)  (node projection)
// mode 1: out bf16 = acc; g_as2/g_ad2 = acc@av_s / acc@av_d
// dyn smem: sW[128*64] + sAt[128*68]
__global__ void __launch_bounds__(128) k_gemm_k128_m64(
        const float* __restrict__ A, const float* __restrict__ W,
        const float* __restrict__ bias,
        const float* __restrict__ av_s, const float* __restrict__ av_d,
        void* __restrict__ outp, int n, int mode) {
    extern __shared__ float sm[];
    float* sW  = sm;              // [128][64]
    float* sAt = sm + 128 * 64;   // [k][r] stride 68
    int t = threadIdx.x;          // 128
    for (int i = t; i < 128 * 64; i += 128) sW[i] = W[i];
    int row0 = blockIdx.x * 64;
    for (int i = t; i < 64 * 128; i += 128) {
        int r = i >> 7, k = i & 127;
        float v = (row0 + r < n) ? A[(size_t)(row0 + r) * 128 + k] : 0.f;
        sAt[k * 68 + r] = v;
    }
    __syncthreads();
    int cg = t & 7, rg = t >> 3;          // 8 col-groups (8 cols) x 16 row-groups (4 rows)
    int c0 = cg * 8, r0 = rg * 4;
    ull acc[4][4];
    #pragma unroll
    for (int r = 0; r < 4; r++)
        #pragma unroll
        for (int c = 0; c < 4; c++) acc[r][c] = 0ULL;
    #pragma unroll 4
    for (int k = 0; k < 128; k++) {
        float4 a4 = *(const float4*)&sAt[k * 68 + r0];
        const ull* wp = (const ull*)&sW[k * 64 + c0];
        ulonglong2 wA = *(const ulonglong2*)wp;        // pairs (c0,c0+1),(c0+2,c0+3)
        ulonglong2 wB = *(const ulonglong2*)(wp + 2);  // pairs (c0+4..c0+7)
        ull a0 = splat2(a4.x), a1 = splat2(a4.y), a2 = splat2(a4.z), a3 = splat2(a4.w);
        fma2(acc[0][0], a0, wA.x); fma2(acc[0][1], a0, wA.y); fma2(acc[0][2], a0, wB.x); fma2(acc[0][3], a0, wB.y);
        fma2(acc[1][0], a1, wA.x); fma2(acc[1][1], a1, wA.y); fma2(acc[1][2], a1, wB.x); fma2(acc[1][3], a1, wB.y);
        fma2(acc[2][0], a2, wA.x); fma2(acc[2][1], a2, wA.y); fma2(acc[2][2], a2, wB.x); fma2(acc[2][3], a2, wB.y);
        fma2(acc[3][0], a3, wA.x); fma2(acc[3][1], a3, wA.y); fma2(acc[3][2], a3, wB.x); fma2(acc[3][3], a3, wB.y);
    }
    if (mode == 0) {
        float* out = (float*)outp;
        float4 bb0 = *(const float4*)&bias[c0];
        float4 bb1 = *(const float4*)&bias[c0 + 4];
        #pragma unroll
        for (int r = 0; r < 4; r++) {
            int row = row0 + r0 + r;
            if (row < n) {
                float2 q0 = u2f(acc[r][0]), q1 = u2f(acc[r][1]);
                float2 q2 = u2f(acc[r][2]), q3 = u2f(acc[r][3]);
                float4 o0 = make_float4(fmaxf(q0.x + bb0.x, 0.f), fmaxf(q0.y + bb0.y, 0.f),
                                        fmaxf(q1.x + bb0.z, 0.f), fmaxf(q1.y + bb0.w, 0.f));
                float4 o1 = make_float4(fmaxf(q2.x + bb1.x, 0.f), fmaxf(q2.y + bb1.y, 0.f),
                                        fmaxf(q3.x + bb1.z, 0.f), fmaxf(q3.y + bb1.w, 0.f));
                *(float4*)&out[(size_t)row * 64 + c0]     = o0;
                *(float4*)&out[(size_t)row * 64 + c0 + 4] = o1;
            }
        }
    } else {
        __nv_bfloat16* out = (__nv_bfloat16*)outp;
        float4 sv0 = *(const float4*)&av_s[c0];
        float4 sv1 = *(const float4*)&av_s[c0 + 4];
        float4 dv0 = *(const float4*)&av_d[c0];
        float4 dv1 = *(const float4*)&av_d[c0 + 4];
        #pragma unroll
        for (int r = 0; r < 4; r++) {
            int row = row0 + r0 + r;
            float2 q0 = u2f(acc[r][0]), q1 = u2f(acc[r][1]);
            float2 q2 = u2f(acc[r][2]), q3 = u2f(acc[r][3]);
            float ps = q0.x*sv0.x + q0.y*sv0.y + q1.x*sv0.z + q1.y*sv0.w
                     + q2.x*sv1.x + q2.y*sv1.y + q3.x*sv1.z + q3.y*sv1.w;
            float pd = q0.x*dv0.x + q0.y*dv0.y + q1.x*dv0.z + q1.y*dv0.w
                     + q2.x*dv1.x + q2.y*dv1.y + q3.x*dv1.z + q3.y*dv1.w;
            // reduce across the 8 col-groups (lane bits 0..2)
            #pragma unroll
            for (int off = 1; off < 8; off <<= 1) {
                ps += __shfl_xor_sync(0xffffffffu, ps, off);
                pd += __shfl_xor_sync(0xffffffffu, pd, off);
            }
            if (row < n) {
                uint4 pk;
                pk.x = pack_bf16x2(q0.x, q0.y);
                pk.y = pack_bf16x2(q1.x, q1.y);
                pk.z = pack_bf16x2(q2.x, q2.y);
                pk.w = pack_bf16x2(q3.x, q3.y);
                *(uint4*)&out[(size_t)row * 64 + c0] = pk;
                if (cg == 0) { g_as2[row] = ps; g_ad2[row] = pd; }
            }
        }
    }
}

// ============ GEMM A[n,64] @ W1[64,128] -> bf16 xh1 + att1, 64 rows/block, 128 thr ============
// column-pair FFMA2, 4 rows x 16 cols per thread.
// dyn smem: sW[64*128] + sAt[64*68]
__global__ void __launch_bounds__(128) k_gemm_k64_m128(
        const float* __restrict__ A, const float* __restrict__ W,
        const float* __restrict__ av_s, const float* __restrict__ av_d,
        __nv_bfloat16* __restrict__ out, int n) {
    extern __shared__ float sm[];
    float* sW  = sm;              // [64][128]
    float* sAt = sm + 64 * 128;   // [k][r] stride 68
    int t = threadIdx.x;          // 128
    for (int i = t; i < 64 * 128; i += 128) sW[i] = W[i];
    int row0 = blockIdx.x * 64;
    for (int i = t; i < 64 * 64; i += 128) {
        int r = i >> 6, k = i & 63;
        float v = (row0 + r < n) ? A[(size_t)(row0 + r) * 64 + k] : 0.f;
        sAt[k * 68 + r] = v;
    }
    __syncthreads();
    int cg = t & 7, rg = t >> 3;          // 8 col-groups (16 cols) x 16 row-groups (4 rows)
    int c0 = cg * 16, r0 = rg * 4;
    ull acc[4][8];
    #pragma unroll
    for (int r = 0; r < 4; r++)
        #pragma unroll
        for (int c = 0; c < 8; c++) acc[r][c] = 0ULL;
    #pragma unroll 2
    for (int k = 0; k < 64; k++) {
        float4 a4 = *(const float4*)&sAt[k * 68 + r0];
        const ull* wp = (const ull*)&sW[k * 128 + c0];
        ulonglong2 w0 = *(const ulonglong2*)wp;
        ulonglong2 w1 = *(const ulonglong2*)(wp + 2);
        ulonglong2 w2 = *(const ulonglong2*)(wp + 4);
        ulonglong2 w3 = *(const ulonglong2*)(wp + 6);
        ull a0 = splat2(a4.x), a1 = splat2(a4.y), a2 = splat2(a4.z), a3 = splat2(a4.w);
        fma2(acc[0][0], a0, w0.x); fma2(acc[0][1], a0, w0.y); fma2(acc[0][2], a0, w1.x); fma2(acc[0][3], a0, w1.y);
        fma2(acc[0][4], a0, w2.x); fma2(acc[0][5], a0, w2.y); fma2(acc[0][6], a0, w3.x); fma2(acc[0][7], a0, w3.y);
        fma2(acc[1][0], a1, w0.x); fma2(acc[1][1], a1, w0.y); fma2(acc[1][2], a1, w1.x); fma2(acc[1][3], a1, w1.y);
        fma2(acc[1][4], a1, w2.x); fma2(acc[1][5], a1, w2.y); fma2(acc[1][6], a1, w3.x); fma2(acc[1][7], a1, w3.y);
        fma2(acc[2][0], a2, w0.x); fma2(acc[2][1], a2, w0.y); fma2(acc[2][2], a2, w1.x); fma2(acc[2][3], a2, w1.y);
        fma2(acc[2][4], a2, w2.x); fma2(acc[2][5], a2, w2.y); fma2(acc[2][6], a2, w3.x); fma2(acc[2][7], a2, w3.y);
        fma2(acc[3][0], a3, w0.x); fma2(acc[3][1], a3, w0.y); fma2(acc[3][2], a3, w1.x); fma2(acc[3][3], a3, w1.y);
        fma2(acc[3][4], a3, w2.x); fma2(acc[3][5], a3, w2.y); fma2(acc[3][6], a3, w3.x); fma2(acc[3][7], a3, w3.y);
    }
    int head = cg >> 1;                   // 16 cols per cg, 32 per head
    float4 s0 = *(const float4*)&av_s[c0];
    float4 s1 = *(const float4*)&av_s[c0 + 4];
    float4 s2 = *(const float4*)&av_s[c0 + 8];
    float4 s3 = *(const float4*)&av_s[c0 + 12];
    float4 d0 = *(const float4*)&av_d[c0];
    float4 d1 = *(const float4*)&av_d[c0 + 4];
    float4 d2 = *(const float4*)&av_d[c0 + 8];
    float4 d3 = *(const float4*)&av_d[c0 + 12];
    #pragma unroll
    for (int r = 0; r < 4; r++) {
        int row = row0 + r0 + r;
        float2 q[8];
        #pragma unroll
        for (int c = 0; c < 8; c++) q[c] = u2f(acc[r][c]);
        float ps = q[0].x*s0.x + q[0].y*s0.y + q[1].x*s0.z + q[1].y*s0.w
                 + q[2].x*s1.x + q[2].y*s1.y + q[3].x*s1.z + q[3].y*s1.w
                 + q[4].x*s2.x + q[4].y*s2.y + q[5].x*s2.z + q[5].y*s2.w
                 + q[6].x*s3.x + q[6].y*s3.y + q[7].x*s3.z + q[7].y*s3.w;
        float pd = q[0].x*d0.x + q[0].y*d0.y + q[1].x*d0.z + q[1].y*d0.w
                 + q[2].x*d1.x + q[2].y*d1.y + q[3].x*d1.z + q[3].y*d1.w
                 + q[4].x*d2.x + q[4].y*d2.y + q[5].x*d2.z + q[5].y*d2.w
                 + q[6].x*d3.x + q[6].y*d3.y + q[7].x*d3.z + q[7].y*d3.w;
        // two cg groups (lane bit 0) form one head (32 cols)
        ps += __shfl_xor_sync(0xffffffffu, ps, 1);
        pd += __shfl_xor_sync(0xffffffffu, pd, 1);
        if (row < n) {
            uint4 pk1, pk2;
            pk1.x = pack_bf16x2(q[0].x, q[0].y); pk1.y = pack_bf16x2(q[1].x, q[1].y);
            pk1.z = pack_bf16x2(q[2].x, q[2].y); pk1.w = pack_bf16x2(q[3].x, q[3].y);
            pk2.x = pack_bf16x2(q[4].x, q[4].y); pk2.y = pack_bf16x2(q[5].x, q[5].y);
            pk2.z = pack_bf16x2(q[6].x, q[6].y); pk2.w = pack_bf16x2(q[7].x, q[7].y);
            *(uint4*)&out[(size_t)row * 128 + c0]     = pk1;
            *(uint4*)&out[(size_t)row * 128 + c0 + 8] = pk2;
            if ((cg & 1) == 0) {
                g_as1[row * 4 + head] = ps;
                g_ad1[row * 4 + head] = pd;
            }
        }
    }
}

// ---------------- GAT1 aggregation: warp per dst node (bf16 payload) ----------------
__global__ void k_agg1(const float* __restrict__ b1, int n) {
    int node = blockIdx.x * 8 + (threadIdx.x >> 5);
    if (node >= n) return;
    int lane = threadIdx.x & 31;
    int h = lane >> 3;
    float ad = g_ad1[node * 4 + h];
    int beg = g_offs[node], end = g_offs[node + 1];
    const uint2* xh = (const uint2*)g_xh1;
    float4 acc[4];
    acc[0] = make_float4(0.f,0.f,0.f,0.f); acc[1] = acc[0]; acc[2] = acc[0]; acc[3] = acc[0];
    float ws[4] = {0.f, 0.f, 0.f, 0.f};
    int j = beg;
    for (; j + 3 < end; j += 4) {
        int s[4];
        s[0] = g_csrc[j]; s[1] = g_csrc[j+1]; s[2] = g_csrc[j+2]; s[3] = g_csrc[j+3];
        #pragma unroll
        for (int u = 0; u < 4; u++) {
            float e = g_as1[s[u] * 4 + h] + ad;
            e = e > 0.f ? e : 0.2f * e;
            float w = __expf(e);
            uint2 pv = xh[(size_t)s[u] * 32 + lane];
            float2 v0 = unpack_bf16x2(pv.x);
            float2 v1 = unpack_bf16x2(pv.y);
            acc[u].x += w*v0.x; acc[u].y += w*v0.y; acc[u].z += w*v1.x; acc[u].w += w*v1.y;
            ws[u] += w;
        }
    }
    for (; j < end; j++) {
        int s0 = g_csrc[j];
        float e = g_as1[s0 * 4 + h] + ad;
        e = e > 0.f ? e : 0.2f * e;
        float w = __expf(e);
        uint2 pv = xh[(size_t)s0 * 32 + lane];
        float2 v0 = unpack_bf16x2(pv.x);
        float2 v1 = unpack_bf16x2(pv.y);
        acc[0].x += w*v0.x; acc[0].y += w*v0.y; acc[0].z += w*v1.x; acc[0].w += w*v1.y;
        ws[0] += w;
    }
    float inv = 1.f / (ws[0] + ws[1] + ws[2] + ws[3] + 1e-16f);
    float4 bb = ((const float4*)b1)[lane];
    float4 o;
    o.x = eluf((acc[0].x + acc[1].x + acc[2].x + acc[3].x) * inv + bb.x);
    o.y = eluf((acc[0].y + acc[1].y + acc[2].y + acc[3].y) * inv + bb.y);
    o.z = eluf((acc[0].z + acc[1].z + acc[2].z + acc[3].z) * inv + bb.z);
    o.w = eluf((acc[0].w + acc[1].w + acc[2].w + acc[3].w) * inv + bb.w);
    ((float4*)g_out1)[(size_t)node * 32 + lane] = o;
}

// ---------------- GAT2 aggregation + elu + mean-pool scatter ----------------
__global__ void k_agg2(const float* __restrict__ b2, const void* __restrict__ batch, int n) {
    int node = blockIdx.x * 8 + (threadIdx.x >> 5);
    if (node >= n) return;
    int lane = threadIdx.x & 31;
    float ad = g_ad2[node];
    int beg = g_offs[node], end = g_offs[node + 1];
    const unsigned* xh = (const unsigned*)g_xh2;
    float2 acc[4];
    acc[0] = make_float2(0.f,0.f); acc[1] = acc[0]; acc[2] = acc[0]; acc[3] = acc[0];
    float ws[4] = {0.f, 0.f, 0.f, 0.f};
    int j = beg;
    for (; j + 3 < end; j += 4) {
        int s[4];
        s[0] = g_csrc[j]; s[1] = g_csrc[j+1]; s[2] = g_csrc[j+2]; s[3] = g_csrc[j+3];
        #pragma unroll
        for (int u = 0; u < 4; u++) {
            float e = g_as2[s[u]] + ad;
            e = e > 0.f ? e : 0.2f * e;
            float w = __expf(e);
            float2 v = unpack_bf16x2(xh[(size_t)s[u] * 32 + lane]);
            acc[u].x += w*v.x; acc[u].y += w*v.y;
            ws[u] += w;
        }
    }
    for (; j < end; j++) {
        int s0 = g_csrc[j];
        float e = g_as2[s0] + ad;
        e = e > 0.f ? e : 0.2f * e;
        float w = __expf(e);
        float2 v = unpack_bf16x2(xh[(size_t)s0 * 32 + lane]);
        acc[0].x += w*v.x; acc[0].y += w*v.y;
        ws[0] += w;
    }
    float inv = 1.f / (ws[0] + ws[1] + ws[2] + ws[3] + 1e-16f);
    float2 bb = ((const float2*)b2)[lane];
    float ox = eluf((acc[0].x + acc[1].x + acc[2].x + acc[3].x) * inv + bb.x);
    float oy = eluf((acc[0].y + acc[1].y + acc[2].y + acc[3].y) * inv + bb.y);
    int b = ld_idx(batch, node, g_is64);
    atomicAdd(&g_pool[b * 64 + lane * 2], ox);
    atomicAdd(&g_pool[b * 64 + lane * 2 + 1], oy);
    if (lane == 0) atomicAdd(&g_cnt[b], 1.0f);
}

// ---------------- graph-level MLP + heads ----------------
__global__ void k_mlp(const float* __restrict__ Wm1, const float* __restrict__ bm1,
                      const float* __restrict__ Wm2, const float* __restrict__ bm2,
                      const float* __restrict__ Wc,  const float* __restrict__ bc,
                      const float* __restrict__ Wr,  const float* __restrict__ br,
                      const float* __restrict__ Wv,  const float* __restrict__ bv,
                      float* __restrict__ out, int G) {
    int g = blockIdx.x;
    int c = threadIdx.x;   // 64 threads
    __shared__ float hg[64], z1[64], z2[64];
    __shared__ float part[6];
    float cnt = fmaxf(g_cnt[g], 1.f);
    hg[c] = g_pool[g * 64 + c] / cnt;
    __syncthreads();
    float acc = bm1[c];
    #pragma unroll 8
    for (int k = 0; k < 64; k++) acc += hg[k] * Wm1[k * 64 + c];
    z1[c] = fmaxf(acc, 0.f);
    __syncthreads();
    acc = bm2[c];
    #pragma unroll 8
    for (int k = 0; k < 64; k++) acc += z1[k] * Wm2[k * 64 + c];
    z2[c] = fmaxf(acc, 0.f);
    __syncthreads();
    float vc = warp_sum(z2[c] * Wc[c]);
    float vr = warp_sum(z2[c] * Wr[c]);
    float vv = warp_sum(z2[c] * Wv[c]);
    if ((c & 31) == 0) {
        int w = c >> 5;
        part[w * 3 + 0] = vc; part[w * 3 + 1] = vr; part[w * 3 + 2] = vv;
    }
    __syncthreads();
    if (c == 0) {
        float cl = part[0] + part[3] + bc[0];
        float rt = part[1] + part[4] + br[0];
        float vo = part[2] + part[5] + bv[0];
        out[g]         = cl;
        out[G + g]     = rt;
        out[2 * G + g] = fmaxf(vo, 0.f) + log1pf(expf(-fabsf(vo)));  // softplus
    }
}

// ---------------- launch ----------------
extern "C" void kernel_launch(void* const* d_in, const int* in_sizes, int n_in,
                              void* d_out, int out_size) {
    const float* x    = (const float*)d_in[0];
    const void*  ei   = d_in[1];
    const void*  batch= d_in[2];
    const float* Wp   = (const float*)d_in[3];
    const float* bp   = (const float*)d_in[4];
    const float* W1   = (const float*)d_in[5];
    const float* as1  = (const float*)d_in[6];
    const float* ad1  = (const float*)d_in[7];
    const float* b1   = (const float*)d_in[8];
    const float* W2   = (const float*)d_in[9];
    const float* as2  = (const float*)d_in[10];
    const float* ad2  = (const float*)d_in[11];
    const float* b2   = (const float*)d_in[12];
    const float* Wm1  = (const float*)d_in[13];
    const float* bm1  = (const float*)d_in[14];
    const float* Wm2  = (const float*)d_in[15];
    const float* bm2  = (const float*)d_in[16];
    const float* Wc   = (const float*)d_in[17];
    const float* bc   = (const float*)d_in[18];
    const float* Wr   = (const float*)d_in[19];
    const float* br   = (const float*)d_in[20];
    const float* Wv   = (const float*)d_in[21];
    const float* bv   = (const float*)d_in[22];
    float* out = (float*)d_out;

    int n  = in_sizes[0] / 128;
    int e  = in_sizes[1] / 2;
    int G  = out_size / 3;
    int et = e + n;

    void *p_h0, *p_xh1, *p_out1, *p_xh2;
    cudaGetSymbolAddress(&p_h0,   g_h0);
    cudaGetSymbolAddress(&p_xh1,  g_xh1);
    cudaGetSymbolAddress(&p_out1, g_out1);
    cudaGetSymbolAddress(&p_xh2,  g_xh2);
    float*         d_h0   = (float*)p_h0;
    __nv_bfloat16* d_xh1  = (__nv_bfloat16*)p_xh1;
    float*         d_out1 = (float*)p_out1;
    __nv_bfloat16* d_xh2  = (__nv_bfloat16*)p_xh2;

    const int G128_SMEM = (128 * 64 + 128 * 68) * (int)sizeof(float);  // 67,584 B
    const int G64_SMEM  = (64 * 128 + 64 * 68)  * (int)sizeof(float);  // 50,176 B
    cudaFuncSetAttribute(k_gemm_k128_m64, cudaFuncAttributeMaxDynamicSharedMemorySize, G128_SMEM);
    cudaFuncSetAttribute(k_gemm_k64_m128, cudaFuncAttributeMaxDynamicSharedMemorySize, G64_SMEM);

    // fork: CSR chain (default) || GEMM chain (s2)
    cudaStream_t s2;
    cudaStreamCreateWithFlags(&s2, cudaStreamNonBlocking);
    cudaEvent_t evFork, evJoin;
    cudaEventCreateWithFlags(&evFork, cudaEventDisableTiming);
    cudaEventCreateWithFlags(&evJoin, cudaEventDisableTiming);

    cudaEventRecord(evFork, 0);
    cudaStreamWaitEvent(s2, evFork, 0);

    // chain B (s2): node projection + xh1 GEMM
    k_gemm_k128_m64<<<(n + 63) / 64, 128, G128_SMEM, s2>>>(x, Wp, bp, nullptr, nullptr, d_h0, n, 0);
    k_gemm_k64_m128<<<(n + 63) / 64, 128, G64_SMEM, s2>>>(d_h0, W1, as1, ad1, d_xh1, n);
    cudaEventRecord(evJoin, s2);

    // chain A (default): init + CSR build
    k_init <<<160, 256>>>(ei, n, G);
    k_hist <<<(et + 1023) / 1024, 256>>>(ei, e, et);
    k_scan <<<1, 1024>>>(n + 1);
    k_place<<<(et + 2047) / 2048, 256>>>(ei, e, et);

    // join
    cudaStreamWaitEvent(0, evJoin, 0);
    k_agg1<<<(n + 7) / 8, 256>>>(b1, n);
    k_gemm_k128_m64<<<(n + 63) / 64, 128, G128_SMEM>>>(d_out1, W2, nullptr, as2, ad2, d_xh2, n, 1);
    k_agg2<<<(n + 7) / 8, 256>>>(b2, batch, n);
    k_mlp<<<G, 64>>>(Wm1, bm1, Wm2, bm2, Wc, bc, Wr, br, Wv, bv, out, G);
}